// round 9
// baseline (speedup 1.0000x reference)
#include <cuda_runtime.h>
#include <cuda_bf16.h>
#include <cstdint>

#define TL 512
#define WN 16
#define HD 64
#define DM 512
#define ATT_SZ (1024*DM)
#define XPLANE (1024*512)
#define WPLANE (896*512)
#define OPLANE (512*512)

#define INV2PI 0.15915494309189535f
#define MAGIC  12582912.0f
#define C2PI_A 6.2831854820251465f

typedef unsigned long long u64;
typedef unsigned int u32;

// ---------------- static scratch ------------------------------------------
__device__ float g_freq [16*TL*WN];
__device__ float g_phase[16*TL*WN];
__device__ float g_amp  [16*TL*WN];
__device__ float g_v    [16*TL*HD];
__device__ float g_att4 [4*ATT_SZ];
__device__ __nv_bfloat16 g_x3 [3*XPLANE];  // x split planes [p][m][k]
__device__ __nv_bfloat16 g_a3 [3*XPLANE];  // attn-out split planes
__device__ __nv_bfloat16 g_w3 [3*WPLANE];  // Wf|Wp|Wa|Wv transposed, [p][n][k]
__device__ __nv_bfloat16 g_wo3[3*OPLANE];  // Wo transposed, [p][n][k]

// pair tables: (A-plane, B-plane) per GEMM accumulation pass
__device__ const int PA_TAB[6] = {0, 0, 1, 1, 0, 2};
__device__ const int PB_TAB[6] = {0, 1, 0, 1, 2, 0};

// ---------------- f32x2 helpers (attn) ------------------------------------
__device__ __forceinline__ u64 pk2(float x, float y) {
    u64 r;
    asm("mov.b64 %0, {%1, %2};" : "=l"(r)
        : "r"(__float_as_uint(x)), "r"(__float_as_uint(y)));
    return r;
}
__device__ __forceinline__ u64 dup2(float x) { return pk2(x, x); }
__device__ __forceinline__ void up2(u64 v, float& x, float& y) {
    unsigned a, b;
    asm("mov.b64 {%0, %1}, %2;" : "=r"(a), "=r"(b) : "l"(v));
    x = __uint_as_float(a); y = __uint_as_float(b);
}
__device__ __forceinline__ u64 f2fma(u64 a, u64 b, u64 c) {
    u64 d; asm("fma.rn.f32x2 %0, %1, %2, %3;" : "=l"(d) : "l"(a), "l"(b), "l"(c));
    return d;
}
__device__ __forceinline__ u64 f2add(u64 a, u64 b) {
    u64 d; asm("add.rn.f32x2 %0, %1, %2;" : "=l"(d) : "l"(a), "l"(b));
    return d;
}
__device__ __forceinline__ u64 f2mul(u64 a, u64 b) {
    u64 d; asm("mul.rn.f32x2 %0, %1, %2;" : "=l"(d) : "l"(a), "l"(b));
    return d;
}
__device__ __forceinline__ void mm4x4(const float4& a4, const ulonglong2& bb,
                                      u64 acc2[4][2]) {
    u64 t;
    t = dup2(a4.x); acc2[0][0] = f2fma(t, bb.x, acc2[0][0]);
                    acc2[0][1] = f2fma(t, bb.y, acc2[0][1]);
    t = dup2(a4.y); acc2[1][0] = f2fma(t, bb.x, acc2[1][0]);
                    acc2[1][1] = f2fma(t, bb.y, acc2[1][1]);
    t = dup2(a4.z); acc2[2][0] = f2fma(t, bb.x, acc2[2][0]);
                    acc2[2][1] = f2fma(t, bb.y, acc2[2][1]);
    t = dup2(a4.w); acc2[3][0] = f2fma(t, bb.x, acc2[3][0]);
                    acc2[3][1] = f2fma(t, bb.y, acc2[3][1]);
}

// ---------------- mma.sync helpers ----------------------------------------
__device__ __forceinline__ u32 smem_u32(const void* p) {
    u32 a;
    asm("{ .reg .u64 t; cvta.to.shared.u64 t, %1; cvt.u32.u64 %0, t; }"
        : "=r"(a) : "l"(p));
    return a;
}
__device__ __forceinline__ void ldsm4(u32 r[4], u32 addr) {
    asm volatile("ldmatrix.sync.aligned.m8n8.x4.shared.b16 {%0,%1,%2,%3}, [%4];"
        : "=r"(r[0]), "=r"(r[1]), "=r"(r[2]), "=r"(r[3]) : "r"(addr));
}
__device__ __forceinline__ void mma16816(float c[4], const u32 a[4],
                                         u32 b0, u32 b1) {
    asm volatile("mma.sync.aligned.m16n8k16.row.col.f32.bf16.bf16.f32 "
        "{%0,%1,%2,%3}, {%4,%5,%6,%7}, {%8,%9}, {%0,%1,%2,%3};"
        : "+f"(c[0]), "+f"(c[1]), "+f"(c[2]), "+f"(c[3])
        : "r"(a[0]), "r"(a[1]), "r"(a[2]), "r"(a[3]), "r"(b0), "r"(b1));
}

// ---------------- 3-term bf16 split ---------------------------------------
__device__ __forceinline__ void split3(float v, __nv_bfloat16& h,
                                       __nv_bfloat16& m_, __nv_bfloat16& l) {
    h  = __float2bfloat16_rn(v);
    float r1 = v - __bfloat162float(h);
    m_ = __float2bfloat16_rn(r1);
    float r2 = r1 - __bfloat162float(m_);
    l  = __float2bfloat16_rn(r2);
}

// ---------------- prep: weight transpose + split to planes -----------------
// grid (22, 8), 128 thr: nn-tile 64 (0-895: proj W's, 896-1407: Wo), k-tile 64
__global__ __launch_bounds__(128)
void wsplit_kernel(const float* __restrict__ Wf, const float* __restrict__ Wp,
                   const float* __restrict__ Wa, const float* __restrict__ Wv,
                   const float* __restrict__ Wo)
{
    __shared__ float t[64][68];
    const int nn0 = blockIdx.x * 64;
    const int k0  = blockIdx.y * 64;
    const int tid = threadIdx.x;

    const float* W; int ldw, c0;
    if      (nn0 < 128) { W = Wf; ldw = 128; c0 = nn0; }
    else if (nn0 < 256) { W = Wp; ldw = 128; c0 = nn0 - 128; }
    else if (nn0 < 384) { W = Wa; ldw = 128; c0 = nn0 - 256; }
    else if (nn0 < 896) { W = Wv; ldw = 512; c0 = nn0 - 384; }
    else                { W = Wo; ldw = 512; c0 = nn0 - 896; }

    {   // load 64k x 64n coalesced, transpose into t[n][k]
        int kr = tid >> 1;
        int cb = (tid & 1) * 32;
        const float* src = W + (size_t)(k0 + kr) * ldw + c0 + cb;
#pragma unroll
        for (int i = 0; i < 8; i++) {
            float4 v = *(const float4*)(src + i * 4);
            t[cb + i*4 + 0][kr] = v.x;
            t[cb + i*4 + 1][kr] = v.y;
            t[cb + i*4 + 2][kr] = v.z;
            t[cb + i*4 + 3][kr] = v.w;
        }
    }
    __syncthreads();
    {   // write n-major rows into 3 planes
        int nr = tid >> 1;
        int kb = (tid & 1) * 32;
        const bool isO = (nn0 >= 896);
        __nv_bfloat16* base = isO
            ? (g_wo3 + (size_t)(nn0 - 896 + nr) * 512)
            : (g_w3  + (size_t)(nn0 + nr) * 512);
        const size_t plane = isO ? OPLANE : WPLANE;
#pragma unroll
        for (int i = 0; i < 8; i++) {
#pragma unroll
            for (int j = 0; j < 4; j++) {
                int k = kb + i*4 + j;
                __nv_bfloat16 h, m_, l;
                split3(t[nr][k], h, m_, l);
                base[k0 + k            ] = h;
                base[k0 + k +     plane] = m_;
                base[k0 + k + 2 * plane] = l;
            }
        }
    }
}

// ---------------- prep: x split --------------------------------------------
__global__ __launch_bounds__(256)
void xsplit_kernel(const float* __restrict__ x)
{
    int idx = blockIdx.x * 256 + threadIdx.x;   // 1024*512
    __nv_bfloat16 h, m_, l;
    split3(x[idx], h, m_, l);
    g_x3[idx] = h; g_x3[idx + XPLANE] = m_; g_x3[idx + 2*XPLANE] = l;
}

// ---------------- prep: attn partial sum + split ---------------------------
__global__ __launch_bounds__(256)
void asplit_kernel()
{
    int idx = blockIdx.x * 256 + threadIdx.x;
    float v = (g_att4[idx] + g_att4[ATT_SZ + idx]) +
              (g_att4[2*ATT_SZ + idx] + g_att4[3*ATT_SZ + idx]);
    __nv_bfloat16 h, m_, l;
    split3(v, h, m_, l);
    g_a3[idx] = h; g_a3[idx + XPLANE] = m_; g_a3[idx + 2*XPLANE] = l;
}

// ---------------- bf16 mma mainloop: acc(128x64) over pair list ------------
// smem: As[2][128][40] bf16 (80B pitch), Bs[2][64][40]; double-buffered BK=32
#define AS_OFF(buf) ((buf) * 10240)
#define BS_OFF(buf) (20480 + (buf) * 5120)

__device__ __forceinline__ void mma_mainloop(
    const __nv_bfloat16* __restrict__ Abase,  // plane-0 of A, [m][512]
    const __nv_bfloat16* __restrict__ Bbase,  // plane-0 of B rows n0.., [n][512]
    size_t aplane, size_t bplane, int npairs,
    char* smraw, u32 sb, int m0, float acc[4][2][4])
{
    const int tid  = threadIdx.x;
    const int wid  = tid >> 5, lane = tid & 31;
    const int mw   = wid >> 2, nw = wid & 3;
    const int sub  = lane & 7, seg = lane >> 3;
    const int niter = npairs * 16;

    // global load indices
    const int arow = tid >> 1, ahalf = tid & 1;     // A: 128 rows x 32B
    const int brow = tid >> 2, bq = tid & 3;        // B: 64 rows x 16B

    uint4 au0, au1, bu;
    {   // preload chunk 0 (pair 0, k0 = 0)
        const __nv_bfloat16* ga = Abase + (size_t)(m0 + arow) * 512 + ahalf * 16;
        au0 = *(const uint4*)(ga);
        au1 = *(const uint4*)(ga + 8);
        bu  = *(const uint4*)(Bbase + (size_t)brow * 512 + bq * 8);
    }

    int buf = 0;
#pragma unroll 1
    for (int it = 0; it < niter; it++) {
        {   // store staged regs
            char* as = smraw + AS_OFF(buf) + arow * 80 + ahalf * 32;
            *(uint4*)(as)      = au0;
            *(uint4*)(as + 16) = au1;
            *(uint4*)(smraw + BS_OFF(buf) + brow * 80 + bq * 16) = bu;
        }
        __syncthreads();
        if (it + 1 < niter) {   // prefetch next chunk
            int nit = it + 1;
            int p = nit >> 4, c = nit & 15;
            const __nv_bfloat16* Ap = Abase + (size_t)PA_TAB[p] * aplane;
            const __nv_bfloat16* Bp = Bbase + (size_t)PB_TAB[p] * bplane;
            int k0 = c * 32;
            const __nv_bfloat16* ga = Ap + (size_t)(m0 + arow) * 512 + k0 + ahalf * 16;
            au0 = *(const uint4*)(ga);
            au1 = *(const uint4*)(ga + 8);
            bu  = *(const uint4*)(Bp + (size_t)brow * 512 + k0 + bq * 8);
        }
        {   // compute 2 k-steps of 16
            u32 a_base = sb + AS_OFF(buf) +
                         (u32)((mw * 64 + (seg & 1) * 8 + sub) * 80 + (seg >> 1) * 16);
#pragma unroll
            for (int ks2 = 0; ks2 < 2; ks2++) {
                u32 ar[4][4];
#pragma unroll
                for (int i = 0; i < 4; i++)
                    ldsm4(ar[i], a_base + i * 1280 + ks2 * 32);
#pragma unroll
                for (int j = 0; j < 2; j++) {
                    int n = nw * 16 + j * 8 + (lane >> 2);
                    const char* bp = smraw + BS_OFF(buf) + n * 80 +
                                     (lane & 3) * 4 + ks2 * 32;
                    u32 b0 = *(const u32*)(bp);
                    u32 b1 = *(const u32*)(bp + 16);
#pragma unroll
                    for (int i = 0; i < 4; i++)
                        mma16816(acc[i][j], ar[i], b0, b1);
                }
            }
        }
        buf ^= 1;
    }
}

// ---------------- stage 1: projections on mma.sync -------------------------
// grid (14 n-tiles of 64, 8 m-tiles of 128), 256 thr
// n-tiles: 0-1 freq, 2-3 phase (6 pairs); 4-5 amp, 6-13 v (3 pairs)
__global__ __launch_bounds__(256)
void proj_mma(const float* __restrict__ bf, const float* __restrict__ bp,
              const float* __restrict__ ba, const float* __restrict__ bv)
{
    __shared__ __align__(16) char smraw[30720];
    const int nt = blockIdx.x, m0 = blockIdx.y * 128;
    const int n0 = nt * 64;
    const int npairs = (nt < 4) ? 6 : 3;

    float acc[4][2][4] = {};
    mma_mainloop(g_x3, g_w3 + (size_t)n0 * 512, XPLANE, WPLANE, npairs,
                 smraw, smem_u32(smraw), m0, acc);

    // epilogue
    const int tid = threadIdx.x, wid = tid >> 5, lane = tid & 31;
    const int mw = wid >> 2, nw = wid & 3;
    const int lr = lane >> 2, lc = (lane & 3) * 2;

    int kind, nloc0; const float* bias;
    if      (nt < 2) { kind = 0; nloc0 = nt * 64;       bias = bf; }
    else if (nt < 4) { kind = 1; nloc0 = (nt - 2) * 64; bias = bp; }
    else if (nt < 6) { kind = 2; nloc0 = (nt - 4) * 64; bias = ba; }
    else             { kind = 3; nloc0 = (nt - 6) * 64; bias = bv; }
    float* dstb = (kind == 0) ? g_freq : (kind == 1) ? g_phase : g_amp;

#pragma unroll
    for (int i = 0; i < 4; i++) {
#pragma unroll
        for (int j = 0; j < 2; j++) {
            int nl = nloc0 + nw * 16 + j * 8 + lc;
            float bb0 = bias[nl], bb1 = bias[nl + 1];
#pragma unroll
            for (int h2 = 0; h2 < 2; h2++) {
                float v0 = acc[i][j][h2*2 + 0] + bb0;
                float v1 = acc[i][j][h2*2 + 1] + bb1;
                int m = m0 + mw * 64 + i * 16 + lr + h2 * 8;
                int b = m >> 9, t = m & 511;
                if (kind == 2) {
                    v0 = fmaxf(v0, 0.f) + log1pf(expf(-fabsf(v0))) + 1e-8f;
                    v1 = fmaxf(v1, 0.f) + log1pf(expf(-fabsf(v1))) + 1e-8f;
                }
                if (kind < 3) {
                    int h = nl >> 4, w = nl & 15;
                    *(float2*)&dstb[(((size_t)(b*8 + h) * TL) + t) * WN + w] =
                        make_float2(v0, v1);
                } else {
                    int h = nl >> 6, d = nl & 63;
                    *(float2*)&g_v[(((size_t)(b*8 + h) * TL) + t) * HD + d] =
                        make_float2(v0, v1);
                }
            }
        }
    }
}

// ---------------- stage 3: output projection on mma.sync -------------------
// grid (8 n-tiles, 8 m-tiles), 256 thr, 3 pairs
__global__ __launch_bounds__(256)
void outp_mma(const float* __restrict__ bo, float* __restrict__ y)
{
    __shared__ __align__(16) char smraw[30720];
    const int n0 = blockIdx.x * 64, m0 = blockIdx.y * 128;

    float acc[4][2][4] = {};
    mma_mainloop(g_a3, g_wo3 + (size_t)n0 * 512, XPLANE, OPLANE, 3,
                 smraw, smem_u32(smraw), m0, acc);

    const int tid = threadIdx.x, wid = tid >> 5, lane = tid & 31;
    const int mw = wid >> 2, nw = wid & 3;
    const int lr = lane >> 2, lc = (lane & 3) * 2;

#pragma unroll
    for (int i = 0; i < 4; i++) {
#pragma unroll
        for (int j = 0; j < 2; j++) {
            int nl = n0 + nw * 16 + j * 8 + lc;
            float bb0 = bo[nl], bb1 = bo[nl + 1];
#pragma unroll
            for (int h2 = 0; h2 < 2; h2++) {
                int m = m0 + mw * 64 + i * 16 + lr + h2 * 8;
                *(float2*)&y[(size_t)m * DM + nl] =
                    make_float2(acc[i][j][h2*2] + bb0, acc[i][j][h2*2+1] + bb1);
            }
        }
    }
}

// ---------------- stage 2: interference attention (unchanged R7) -----------
__global__ __launch_bounds__(256, 2)
void attn4_kernel()
{
    __shared__ float s_fpa[64 * 52];
    __shared__ float s_s2p[64 * 4];
    __shared__ float s_att[64 * 68];
    __shared__ float s_v  [64 * 68];

    const int bh = blockIdx.x;
    const int qt = 7 - blockIdx.y;
    const int s  = blockIdx.z;
    const int tid = threadIdx.x;
    const int qa = tid >> 2;
    const int g  = tid & 3;
    const int ty = tid >> 4;
    const int tx = tid & 15;
    const int qglob = qt * 64 + qa;
    const int b = bh >> 3, h = bh & 7;

    u64 fq2[8], pq2[8], aq2[8];
    {
        const ulonglong2* f2 = (const ulonglong2*)(g_freq  + (((size_t)bh*TL) + qglob) * WN);
        const ulonglong2* p2 = (const ulonglong2*)(g_phase + (((size_t)bh*TL) + qglob) * WN);
        const ulonglong2* a2 = (const ulonglong2*)(g_amp   + (((size_t)bh*TL) + qglob) * WN);
#pragma unroll
        for (int i = 0; i < 4; i++) {
            ulonglong2 t;
            t = f2[i]; fq2[2*i] = t.x; fq2[2*i+1] = t.y;
            t = p2[i]; pq2[2*i] = t.x; pq2[2*i+1] = t.y;
            t = a2[i]; aq2[2*i] = t.x; aq2[2*i+1] = t.y;
        }
    }
    float s2q;
    {
        u64 s2 = 0ull;
#pragma unroll
        for (int i = 0; i < 8; i++) s2 = f2fma(aq2[i], aq2[i], s2);
        float lo, hi; up2(s2, lo, hi); s2q = lo + hi;
    }

    const u64 inv2pi2 = dup2(INV2PI);
    const u64 magic2  = dup2(MAGIC);
    const u64 nmagic2 = dup2(-MAGIC);
    const u64 nc2pi2  = dup2(-C2PI_A);

    u64 acc2[4][2] = {};

#pragma unroll 1
    for (int kt = s * 64; kt < (qt + 1) * 64; kt += 256) {
        __syncthreads();
        {
            int row = tid >> 2, c4 = (tid & 3) << 2;
            size_t base = ((size_t)bh * TL + (kt + row)) * WN + c4;
            float4 f = *(const float4*)(g_freq  + base);
            float4 p = *(const float4*)(g_phase + base);
            float4 a = *(const float4*)(g_amp   + base);
            *(float4*)&s_fpa[row*52 +      c4] = make_float4(-f.x, -f.y, -f.z, -f.w);
            *(float4*)&s_fpa[row*52 + 16 + c4] = make_float4(-p.x, -p.y, -p.z, -p.w);
            *(float4*)&s_fpa[row*52 + 32 + c4] = a;
            s_s2p[row*4 + (tid & 3)] = a.x*a.x + a.y*a.y + a.z*a.z + a.w*a.w;
#pragma unroll
            for (int i = 0; i < 4; i++) {
                int l = tid + i * 256;
                int r = l >> 4, cc = (l & 15) << 2;
                *(float4*)&s_v[r*68 + cc] =
                    *(const float4*)(g_v + ((size_t)bh*TL + (kt + r)) * HD + cc);
            }
        }
        __syncthreads();

#pragma unroll 1
        for (int j = 0; j < 16; j++) {
            int kl = g + (j << 2);
            int kg = kt + kl;
            float attv = 0.f;
            if (kg <= qglob) {
                const float dtv = (float)(qglob - kg);
                const u64 dt2 = dup2(dtv);
                const float* fk = &s_fpa[kl * 52];
                float4 s2p = *(const float4*)&s_s2p[kl * 4];
                float s2k = (s2p.x + s2p.y) + (s2p.z + s2p.w);
                u64 cacc2 = 0ull, dacc2 = 0ull;
#pragma unroll
                for (int g4 = 0; g4 < 4; g4++) {
                    ulonglong2 nf = *(const ulonglong2*)(fk +      (g4 << 2));
                    ulonglong2 np = *(const ulonglong2*)(fk + 16 + (g4 << 2));
                    ulonglong2 aa = *(const ulonglong2*)(fk + 32 + (g4 << 2));
#pragma unroll
                    for (int half = 0; half < 2; half++) {
                        int wp = 2*g4 + half;
                        u64 nfp = half ? nf.y : nf.x;
                        u64 npp = half ? np.y : np.x;
                        u64 aap = half ? aa.y : aa.x;
                        u64 dw  = f2add(fq2[wp], nfp);
                        u64 dp  = f2add(pq2[wp], npp);
                        u64 arg = f2fma(dw, dt2, dp);
                        u64 tr  = f2fma(arg, inv2pi2, magic2);
                        u64 nn  = f2add(tr, nmagic2);
                        u64 rr  = f2fma(nn, nc2pi2, arg);
                        float r0, r1; up2(rr, r0, r1);
                        u64 cs  = pk2(__cosf(r0), __cosf(r1));
                        u64 pp  = f2mul(aq2[wp], aap);
                        dacc2 = f2add(dacc2, pp);
                        cacc2 = f2fma(pp, cs, cacc2);
                    }
                }
                float c0, c1, d0, d1;
                up2(cacc2, c0, c1); up2(dacc2, d0, d1);
                float cacc = c0 + c1, dacc = d0 + d1;
                float S  = s2q + s2k;
                float it = fmaf(2.f, cacc, S);
                float en = fmaf(2.f, dacc, S) + 1e-8f;
                attv = __fdividef(it, en);
            }
            s_att[kl * 68 + qa] = attv;
        }
        __syncthreads();

#pragma unroll 4
        for (int kk = 0; kk < 64; kk++) {
            float4 a4 = *(const float4*)&s_att[kk*68 + (ty << 2)];
            ulonglong2 vv = *(const ulonglong2*)&s_v[kk*68 + (tx << 2)];
            mm4x4(a4, vv, acc2);
        }
    }

    float* dst = g_att4 + (size_t)s * ATT_SZ;
#pragma unroll
    for (int i = 0; i < 4; i++) {
        float c0, c1, c2, c3;
        up2(acc2[i][0], c0, c1);
        up2(acc2[i][1], c2, c3);
        int row = qt * 64 + (ty << 2) + i;
        *(float4*)&dst[((size_t)(b * TL + row)) * DM + h * HD + (tx << 2)] =
            make_float4(c0, c1, c2, c3);
    }
}

// ---------------- launch ----------------------------------------------------
extern "C" void kernel_launch(void* const* d_in, const int* in_sizes, int n_in,
                              void* d_out, int out_size)
{
    const float* x  = (const float*)d_in[0];
    const float* Wf = (const float*)d_in[1];
    const float* bf = (const float*)d_in[2];
    const float* Wp = (const float*)d_in[3];
    const float* bp = (const float*)d_in[4];
    const float* Wa = (const float*)d_in[5];
    const float* ba = (const float*)d_in[6];
    const float* Wv = (const float*)d_in[7];
    const float* bv = (const float*)d_in[8];
    const float* Wo = (const float*)d_in[9];
    const float* bo = (const float*)d_in[10];
    float* y = (float*)d_out;

    wsplit_kernel<<<dim3(22, 8), 128>>>(Wf, Wp, Wa, Wv, Wo);
    xsplit_kernel<<<2048, 256>>>(x);
    proj_mma<<<dim3(14, 8), 256>>>(bf, bp, ba, bv);
    attn4_kernel<<<dim3(16, 8, 4), 256>>>();
    asplit_kernel<<<2048, 256>>>();
    outp_mma<<<dim3(8, 8), 256>>>(bo, y);
}

// round 10
// speedup vs baseline: 1.5299x; 1.5299x over previous
#include <cuda_runtime.h>

#define TL 512
#define WN 16
#define HD 64
#define DM 512
#define ATT_SZ (1024*DM)
#define PP_SZ  (1024*896)

#define INV2PI 0.15915494309189535f
#define MAGIC  12582912.0f
#define C2PI_A 6.2831854820251465f

typedef unsigned long long u64;
typedef unsigned int u32;

// ---------------- static scratch (no allocation) ---------------------------
__device__ float g_freq [16*TL*WN];
__device__ float g_phase[16*TL*WN];
__device__ float g_amp  [16*TL*WN];
__device__ float g_v    [16*TL*HD];
__device__ float g_att4 [4*ATT_SZ];
__device__ float g_pp   [2*PP_SZ];    // proj partials, [z][m][896]

// ---------------- f32x2 packed helpers -------------------------------------
__device__ __forceinline__ u64 pk2(float x, float y) {
    u64 r;
    asm("mov.b64 %0, {%1, %2};" : "=l"(r)
        : "r"(__float_as_uint(x)), "r"(__float_as_uint(y)));
    return r;
}
__device__ __forceinline__ u64 dup2(float x) { return pk2(x, x); }
__device__ __forceinline__ void up2(u64 v, float& x, float& y) {
    unsigned a, b;
    asm("mov.b64 {%0, %1}, %2;" : "=r"(a), "=r"(b) : "l"(v));
    x = __uint_as_float(a); y = __uint_as_float(b);
}
__device__ __forceinline__ u64 f2fma(u64 a, u64 b, u64 c) {
    u64 d; asm("fma.rn.f32x2 %0, %1, %2, %3;" : "=l"(d) : "l"(a), "l"(b), "l"(c));
    return d;
}
__device__ __forceinline__ u64 f2add(u64 a, u64 b) {
    u64 d; asm("add.rn.f32x2 %0, %1, %2;" : "=l"(d) : "l"(a), "l"(b));
    return d;
}
__device__ __forceinline__ u64 f2mul(u64 a, u64 b) {
    u64 d; asm("mul.rn.f32x2 %0, %1, %2;" : "=l"(d) : "l"(a), "l"(b));
    return d;
}
__device__ __forceinline__ void mm4x4(const float4& a4, const ulonglong2& bb,
                                      u64 acc2[4][2]) {
    u64 t;
    t = dup2(a4.x); acc2[0][0] = f2fma(t, bb.x, acc2[0][0]);
                    acc2[0][1] = f2fma(t, bb.y, acc2[0][1]);
    t = dup2(a4.y); acc2[1][0] = f2fma(t, bb.x, acc2[1][0]);
                    acc2[1][1] = f2fma(t, bb.y, acc2[1][1]);
    t = dup2(a4.z); acc2[2][0] = f2fma(t, bb.x, acc2[2][0]);
                    acc2[2][1] = f2fma(t, bb.y, acc2[2][1]);
    t = dup2(a4.w); acc2[3][0] = f2fma(t, bb.x, acc2[3][0]);
                    acc2[3][1] = f2fma(t, bb.y, acc2[3][1]);
}

// ---------------- GEMM core with k-range, 64x64 tile, dbl-buffered ---------
__device__ __forceinline__ void gemm64k(const float* __restrict__ A,
                                        const float* __restrict__ W, int ldw,
                                        int m0, int n0, int kbeg, int kend,
                                        u64 acc2[4][2])
{
    __shared__ float As[2][16][68];
    __shared__ float Ws[2][16][68];
    const int tid = threadIdx.x;
    const int lm  = tid >> 2;
    const int lk4 = (tid & 3) << 2;
    const int lkk = tid >> 4;
    const int ln4 = (tid & 15) << 2;
    const int tx  = tid & 15;
    const int ty  = tid >> 4;

    const float* Ar = A + (size_t)(m0 + lm) * DM + lk4;
    const float* Wb = W + (size_t)lkk * ldw + n0 + ln4;

    float4 a = *(const float4*)(Ar + kbeg);
    float4 w = *(const float4*)(Wb + (size_t)kbeg * ldw);

    int buf = 0;
#pragma unroll 1
    for (int k0 = kbeg; k0 < kend; k0 += 16) {
        As[buf][lk4 + 0][lm] = a.x;
        As[buf][lk4 + 1][lm] = a.y;
        As[buf][lk4 + 2][lm] = a.z;
        As[buf][lk4 + 3][lm] = a.w;
        *(float4*)&Ws[buf][lkk][ln4] = w;
        __syncthreads();
        if (k0 + 16 < kend) {
            a = *(const float4*)(Ar + k0 + 16);
            w = *(const float4*)(Wb + (size_t)(k0 + 16) * ldw);
        }
#pragma unroll
        for (int kk = 0; kk < 16; kk++) {
            float4 a4 = *(const float4*)&As[buf][kk][ty << 2];
            ulonglong2 bb = *(const ulonglong2*)&Ws[buf][kk][tx << 2];
            mm4x4(a4, bb, acc2);
        }
        buf ^= 1;
    }
}

// ---------------- stage 1a: projection GEMM, split-K=2, 448 CTAs -----------
// grid (14, 16, 2): n-tiles 0-1 Wf, 2-3 Wp, 4-5 Wa, 6-13 Wv; z = k-half
__global__ __launch_bounds__(256, 3)
void proj_split(const float* __restrict__ x,
                const float* __restrict__ Wf, const float* __restrict__ Wp,
                const float* __restrict__ Wa, const float* __restrict__ Wv)
{
    const int nt = blockIdx.x;
    const int m0 = blockIdx.y * 64;
    const int z  = blockIdx.z;
    const float* W; int ldw, nc0;
    if      (nt < 2) { W = Wf; ldw = 128; nc0 = nt*64;       }
    else if (nt < 4) { W = Wp; ldw = 128; nc0 = nt*64 - 128; }
    else if (nt < 6) { W = Wa; ldw = 128; nc0 = nt*64 - 256; }
    else             { W = Wv; ldw = 512; nc0 = nt*64 - 384; }

    u64 acc2[4][2] = {};
    gemm64k(x, W, ldw, m0, nc0, z * 256, z * 256 + 256, acc2);

    // raw partial store to [m][896] at global col nt*64
    float* dst = g_pp + (size_t)z * PP_SZ;
    const int tx = threadIdx.x & 15, ty = threadIdx.x >> 4;
    const int gcol = nt * 64 + (tx << 2);
#pragma unroll
    for (int i = 0; i < 4; i++) {
        float c0, c1, c2, c3;
        up2(acc2[i][0], c0, c1);
        up2(acc2[i][1], c2, c3);
        int m = m0 + (ty << 2) + i;
        *(float4*)&dst[(size_t)m * 896 + gcol] = make_float4(c0, c1, c2, c3);
    }
}

// ---------------- stage 1b: reduce + bias + softplus + scatter -------------
// grid 1024 (one per m-row), 224 threads (one float4 per thread)
__global__ __launch_bounds__(224)
void projred(const float* __restrict__ bf, const float* __restrict__ bp,
             const float* __restrict__ ba, const float* __restrict__ bv)
{
    const int m   = blockIdx.x;
    const int col = threadIdx.x * 4;           // 0..892
    const size_t off = (size_t)m * 896 + col;
    float4 p0 = *(const float4*)(g_pp + off);
    float4 p1 = *(const float4*)(g_pp + PP_SZ + off);
    const int b = m >> 9, t = m & 511;

    const float* bias; int lc; int kind;
    if      (col < 128) { bias = bf; lc = col;       kind = 0; }
    else if (col < 256) { bias = bp; lc = col - 128; kind = 1; }
    else if (col < 384) { bias = ba; lc = col - 256; kind = 2; }
    else                { bias = bv; lc = col - 384; kind = 3; }

    float4 bb = *(const float4*)(bias + lc);
    float v0 = (p0.x + p1.x) + bb.x;
    float v1 = (p0.y + p1.y) + bb.y;
    float v2 = (p0.z + p1.z) + bb.z;
    float v3 = (p0.w + p1.w) + bb.w;

    if (kind == 2) {
        v0 = fmaxf(v0, 0.f) + log1pf(expf(-fabsf(v0))) + 1e-8f;
        v1 = fmaxf(v1, 0.f) + log1pf(expf(-fabsf(v1))) + 1e-8f;
        v2 = fmaxf(v2, 0.f) + log1pf(expf(-fabsf(v2))) + 1e-8f;
        v3 = fmaxf(v3, 0.f) + log1pf(expf(-fabsf(v3))) + 1e-8f;
    }
    float4 out = make_float4(v0, v1, v2, v3);

    if (kind < 3) {
        int h = lc >> 4, w = lc & 15;
        float* dstb = (kind == 0) ? g_freq : (kind == 1) ? g_phase : g_amp;
        *(float4*)&dstb[(((size_t)(b*8 + h) * TL) + t) * WN + w] = out;
    } else {
        int h = lc >> 6, d = lc & 63;
        *(float4*)&g_v[(((size_t)(b*8 + h) * TL) + t) * HD + d] = out;
    }
}

// ---------------- stage 2: interference attention (R7, unchanged) ----------
__global__ __launch_bounds__(256, 2)
void attn4_kernel()
{
    __shared__ float s_fpa[64 * 52];
    __shared__ float s_s2p[64 * 4];
    __shared__ float s_att[64 * 68];
    __shared__ float s_v  [64 * 68];

    const int bh = blockIdx.x;
    const int qt = 7 - blockIdx.y;
    const int s  = blockIdx.z;
    const int tid = threadIdx.x;
    const int qa = tid >> 2;
    const int g  = tid & 3;
    const int ty = tid >> 4;
    const int tx = tid & 15;
    const int qglob = qt * 64 + qa;
    const int b = bh >> 3, h = bh & 7;

    u64 fq2[8], pq2[8], aq2[8];
    {
        const ulonglong2* f2 = (const ulonglong2*)(g_freq  + (((size_t)bh*TL) + qglob) * WN);
        const ulonglong2* p2 = (const ulonglong2*)(g_phase + (((size_t)bh*TL) + qglob) * WN);
        const ulonglong2* a2 = (const ulonglong2*)(g_amp   + (((size_t)bh*TL) + qglob) * WN);
#pragma unroll
        for (int i = 0; i < 4; i++) {
            ulonglong2 t;
            t = f2[i]; fq2[2*i] = t.x; fq2[2*i+1] = t.y;
            t = p2[i]; pq2[2*i] = t.x; pq2[2*i+1] = t.y;
            t = a2[i]; aq2[2*i] = t.x; aq2[2*i+1] = t.y;
        }
    }
    float s2q;
    {
        u64 s2 = 0ull;
#pragma unroll
        for (int i = 0; i < 8; i++) s2 = f2fma(aq2[i], aq2[i], s2);
        float lo, hi; up2(s2, lo, hi); s2q = lo + hi;
    }

    const u64 inv2pi2 = dup2(INV2PI);
    const u64 magic2  = dup2(MAGIC);
    const u64 nmagic2 = dup2(-MAGIC);
    const u64 nc2pi2  = dup2(-C2PI_A);

    u64 acc2[4][2] = {};

#pragma unroll 1
    for (int kt = s * 64; kt < (qt + 1) * 64; kt += 256) {
        __syncthreads();
        {
            int row = tid >> 2, c4 = (tid & 3) << 2;
            size_t base = ((size_t)bh * TL + (kt + row)) * WN + c4;
            float4 f = *(const float4*)(g_freq  + base);
            float4 p = *(const float4*)(g_phase + base);
            float4 a = *(const float4*)(g_amp   + base);
            *(float4*)&s_fpa[row*52 +      c4] = make_float4(-f.x, -f.y, -f.z, -f.w);
            *(float4*)&s_fpa[row*52 + 16 + c4] = make_float4(-p.x, -p.y, -p.z, -p.w);
            *(float4*)&s_fpa[row*52 + 32 + c4] = a;
            s_s2p[row*4 + (tid & 3)] = a.x*a.x + a.y*a.y + a.z*a.z + a.w*a.w;
#pragma unroll
            for (int i = 0; i < 4; i++) {
                int l = tid + i * 256;
                int r = l >> 4, cc = (l & 15) << 2;
                *(float4*)&s_v[r*68 + cc] =
                    *(const float4*)(g_v + ((size_t)bh*TL + (kt + r)) * HD + cc);
            }
        }
        __syncthreads();

#pragma unroll 1
        for (int j = 0; j < 16; j++) {
            int kl = g + (j << 2);
            int kg = kt + kl;
            float attv = 0.f;
            if (kg <= qglob) {
                const float dtv = (float)(qglob - kg);
                const u64 dt2 = dup2(dtv);
                const float* fk = &s_fpa[kl * 52];
                float4 s2p = *(const float4*)&s_s2p[kl * 4];
                float s2k = (s2p.x + s2p.y) + (s2p.z + s2p.w);
                u64 cacc2 = 0ull, dacc2 = 0ull;
#pragma unroll
                for (int g4 = 0; g4 < 4; g4++) {
                    ulonglong2 nf = *(const ulonglong2*)(fk +      (g4 << 2));
                    ulonglong2 np = *(const ulonglong2*)(fk + 16 + (g4 << 2));
                    ulonglong2 aa = *(const ulonglong2*)(fk + 32 + (g4 << 2));
#pragma unroll
                    for (int half = 0; half < 2; half++) {
                        int wp = 2*g4 + half;
                        u64 nfp = half ? nf.y : nf.x;
                        u64 npp = half ? np.y : np.x;
                        u64 aap = half ? aa.y : aa.x;
                        u64 dw  = f2add(fq2[wp], nfp);
                        u64 dp  = f2add(pq2[wp], npp);
                        u64 arg = f2fma(dw, dt2, dp);
                        u64 tr  = f2fma(arg, inv2pi2, magic2);
                        u64 nn  = f2add(tr, nmagic2);
                        u64 rr  = f2fma(nn, nc2pi2, arg);
                        float r0, r1; up2(rr, r0, r1);
                        u64 cs  = pk2(__cosf(r0), __cosf(r1));
                        u64 pp  = f2mul(aq2[wp], aap);
                        dacc2 = f2add(dacc2, pp);
                        cacc2 = f2fma(pp, cs, cacc2);
                    }
                }
                float c0, c1, d0, d1;
                up2(cacc2, c0, c1); up2(dacc2, d0, d1);
                float cacc = c0 + c1, dacc = d0 + d1;
                float S  = s2q + s2k;
                float it = fmaf(2.f, cacc, S);
                float en = fmaf(2.f, dacc, S) + 1e-8f;
                attv = __fdividef(it, en);
            }
            s_att[kl * 68 + qa] = attv;
        }
        __syncthreads();

#pragma unroll 4
        for (int kk = 0; kk < 64; kk++) {
            float4 a4 = *(const float4*)&s_att[kk*68 + (ty << 2)];
            ulonglong2 vv = *(const ulonglong2*)&s_v[kk*68 + (tx << 2)];
            mm4x4(a4, vv, acc2);
        }
    }

    float* dst = g_att4 + (size_t)s * ATT_SZ;
#pragma unroll
    for (int i = 0; i < 4; i++) {
        float c0, c1, c2, c3;
        up2(acc2[i][0], c0, c1);
        up2(acc2[i][1], c2, c3);
        int row = qt * 64 + (ty << 2) + i;
        *(float4*)&dst[((size_t)(b * TL + row)) * DM + h * HD + (tx << 2)] =
            make_float4(c0, c1, c2, c3);
    }
}

// ---------------- stage 3: output projection (R7, unchanged) ---------------
__global__ __launch_bounds__(256)
void outp4_kernel(const float* __restrict__ Wo,
                  const float* __restrict__ bo,
                  float* __restrict__ y)
{
    __shared__ float As[2][16][68];
    __shared__ float Ws[2][16][68];
    const int n0 = blockIdx.x * 64;
    const int m0 = blockIdx.y * 64;
    const int tid = threadIdx.x;
    const int lm  = tid >> 2;
    const int lk4 = (tid & 3) << 2;
    const int lkk = tid >> 4;
    const int ln4 = (tid & 15) << 2;
    const int tx  = tid & 15;
    const int ty  = tid >> 4;

    const size_t abase = (size_t)(m0 + lm) * DM + lk4;
    const float* Wb = Wo + (size_t)lkk * DM + n0 + ln4;

    u64 acc2[4][2] = {};

    ulonglong2 a;
    {
        ulonglong2 a0 = *(const ulonglong2*)(g_att4 + 0*ATT_SZ + abase);
        ulonglong2 a1 = *(const ulonglong2*)(g_att4 + 1*ATT_SZ + abase);
        ulonglong2 a2 = *(const ulonglong2*)(g_att4 + 2*ATT_SZ + abase);
        ulonglong2 a3 = *(const ulonglong2*)(g_att4 + 3*ATT_SZ + abase);
        a.x = f2add(f2add(a0.x, a1.x), f2add(a2.x, a3.x));
        a.y = f2add(f2add(a0.y, a1.y), f2add(a2.y, a3.y));
    }
    float4 w = *(const float4*)(Wb);

    int buf = 0;
#pragma unroll 1
    for (int k0 = 0; k0 < 512; k0 += 16) {
        {
            float s0, s1, s2, s3;
            up2(a.x, s0, s1); up2(a.y, s2, s3);
            As[buf][lk4 + 0][lm] = s0;
            As[buf][lk4 + 1][lm] = s1;
            As[buf][lk4 + 2][lm] = s2;
            As[buf][lk4 + 3][lm] = s3;
        }
        *(float4*)&Ws[buf][lkk][ln4] = w;
        __syncthreads();
        if (k0 + 16 < 512) {
            ulonglong2 a0 = *(const ulonglong2*)(g_att4 + 0*ATT_SZ + abase + k0 + 16);
            ulonglong2 a1 = *(const ulonglong2*)(g_att4 + 1*ATT_SZ + abase + k0 + 16);
            ulonglong2 a2 = *(const ulonglong2*)(g_att4 + 2*ATT_SZ + abase + k0 + 16);
            ulonglong2 a3 = *(const ulonglong2*)(g_att4 + 3*ATT_SZ + abase + k0 + 16);
            a.x = f2add(f2add(a0.x, a1.x), f2add(a2.x, a3.x));
            a.y = f2add(f2add(a0.y, a1.y), f2add(a2.y, a3.y));
            w = *(const float4*)(Wb + (size_t)(k0 + 16) * DM);
        }
#pragma unroll
        for (int kk = 0; kk < 16; kk++) {
            float4 a4 = *(const float4*)&As[buf][kk][ty << 2];
            ulonglong2 bb = *(const ulonglong2*)&Ws[buf][kk][tx << 2];
            mm4x4(a4, bb, acc2);
        }
        buf ^= 1;
    }

#pragma unroll
    for (int i = 0; i < 4; i++) {
        float c0, c1, c2, c3;
        up2(acc2[i][0], c0, c1);
        up2(acc2[i][1], c2, c3);
        int m = m0 + (ty << 2) + i;
        int n = n0 + (tx << 2);
        float4 bb = *(const float4*)(bo + n);
        *(float4*)&y[(size_t)m * DM + n] =
            make_float4(c0 + bb.x, c1 + bb.y, c2 + bb.z, c3 + bb.w);
    }
}

// ---------------- launch ----------------------------------------------------
extern "C" void kernel_launch(void* const* d_in, const int* in_sizes, int n_in,
                              void* d_out, int out_size)
{
    const float* x  = (const float*)d_in[0];
    const float* Wf = (const float*)d_in[1];
    const float* bf = (const float*)d_in[2];
    const float* Wp = (const float*)d_in[3];
    const float* bp = (const float*)d_in[4];
    const float* Wa = (const float*)d_in[5];
    const float* ba = (const float*)d_in[6];
    const float* Wv = (const float*)d_in[7];
    const float* bv = (const float*)d_in[8];
    const float* Wo = (const float*)d_in[9];
    const float* bo = (const float*)d_in[10];
    float* y = (float*)d_out;

    proj_split<<<dim3(14, 16, 2), 256>>>(x, Wf, Wp, Wa, Wv);
    projred<<<1024, 224>>>(bf, bp, ba, bv);
    attn4_kernel<<<dim3(16, 8, 4), 256>>>();
    outp4_kernel<<<dim3(8, 16), 256>>>(Wo, bo, y);
}